// round 11
// baseline (speedup 1.0000x reference)
#include <cuda_runtime.h>
#include <stdint.h>

// Output layout: fine_data [N*8, 64] f32, then fine_ijk [N*8, 3] written as f32
// (coords < 1024, exactly representable in f32).
//
// Converged structure (R2), final geometry sweep: 512 threads / 32 coarse rows
// per block (8192 blocks). Per-thread work identical to the proven kernel:
//   - data: thread t -> coarse float4 idx = bid*512+t; one load, replicated to
//           the 8 fine rows (stride 64 floats). Serial load->store (MLP_p1=1).
//   - ijk:  threads 0..191 each write one float4 of the ijk region
//           (32 rows * 24 floats = 192 float4 per block).
//
// Falsified: .cs hints (R3), 256-bit ld/st (R4), MLP=4 batching (R5),
// persistent single-wave (R9, -13us). Roofline: 632 MB mandatory traffic at
// ~6.78 TB/s app throughput = 85% of HBM3e spec on an 89%-write stream.

__global__ void __launch_bounds__(512) upsample_fused_kernel(
    const float4* __restrict__ src,     // coarse_data as float4, N*16 elems
    const int* __restrict__ ijk,        // coarse_ijk, N*3 ints
    float4* __restrict__ dst_data,      // fine_data as float4
    float4* __restrict__ dst_ijk,       // fine_ijk region as float4
    int n)
{
    const int t   = threadIdx.x;
    const int bid = blockIdx.x;

    // ---------- data replication ----------
    {
        int idx = bid * 512 + t;                 // coarse float4 index
        if (idx < n * 16) {
            int chunk = idx & 15;
            long long cr = idx >> 4;
            float4 v = src[idx];
            float4* base = dst_data + cr * 128 + chunk; // 8 fine rows * 16 f4
#pragma unroll
            for (int j = 0; j < 8; j++) {
                base[j * 16] = v;
            }
        }
    }

    // ---------- ijk expansion ----------
    // Block covers coarse rows [bid*32, bid*32+32) -> 192 float4 of ijk output.
    if (t < 192) {
        long long q = (long long)bid * 192 + t;     // float4 index in ijk region
        if (q < (long long)n * 6) {
            long long e0 = q * 4;                   // first float element index
            float vals[4];
#pragma unroll
            for (int k = 0; k < 4; k++) {
                long long e = e0 + k;
                long long f = e / 3;                // fine voxel index
                int comp    = (int)(e - f * 3);     // 0,1,2
                long long cr = f >> 3;              // coarse row
                int sub      = (int)(f & 7);        // sub-voxel 0..7
                int c = ijk[cr * 3 + comp];
                int off = (sub >> (2 - comp)) & 1;  // meshgrid ij order
                vals[k] = (float)(2 * c + off);
            }
            dst_ijk[q] = make_float4(vals[0], vals[1], vals[2], vals[3]);
        }
    }
}

extern "C" void kernel_launch(void* const* d_in, const int* in_sizes, int n_in,
                              void* d_out, int out_size) {
    const float* coarse_data = (const float*)d_in[0];
    const int*   coarse_ijk  = (const int*)d_in[1];
    float* out = (float*)d_out;

    int n = in_sizes[0] / 64;                       // coarse voxel count
    long long data_elems = (long long)n * 8 * 64;   // fine_data float count

    float4* dst_data = (float4*)out;
    float4* dst_ijk  = (float4*)(out + data_elems);

    int blocks = (n + 31) / 32;                     // 32 coarse rows per block
    upsample_fused_kernel<<<blocks, 512>>>((const float4*)coarse_data,
                                           coarse_ijk, dst_data, dst_ijk, n);
}

// round 12
// speedup vs baseline: 1.0129x; 1.0129x over previous
#include <cuda_runtime.h>
#include <stdint.h>

// Output layout: fine_data [N*8, 64] f32, then fine_ijk [N*8, 3] written as f32
// (coords < 1024, exactly representable in f32).
//
// FINAL kernel (converged over 11 rounds): fused, 256 threads / 16 coarse rows
// per block, 16384 small independent CTAs.
//   - data: thread t -> coarse float4 idx = bid*256+t; one load, replicated to
//           the 8 fine rows (stride 64 floats). Serial load->store (MLP_p1=1).
//   - ijk:  threads 0..95 each write one float4 of the ijk region
//           (16 rows * 24 floats = 96 float4 per block).
//
// Falsified alternatives: .cs evict-first (R3), 256-bit ld/st (R4), MLP=4
// front-batch (R5), persistent single-wave (R9: -13us, serialized tiles reduce
// per-SM store parallelism), 512-thread blocks (R11: occupancy dip).
// Roofline: 632 MB mandatory, reuse-free traffic at ~6.78 TB/s app throughput
// = 85% of 8 TB/s HBM3e on an 89%-write stream. DRAM is the only saturated
// resource (issue <9%, L2 ~51%, compute ~0%). Converged.

__global__ void __launch_bounds__(256) upsample_fused_kernel(
    const float4* __restrict__ src,     // coarse_data as float4, N*16 elems
    const int* __restrict__ ijk,        // coarse_ijk, N*3 ints
    float4* __restrict__ dst_data,      // fine_data as float4
    float4* __restrict__ dst_ijk,       // fine_ijk region as float4
    int n)
{
    const int t   = threadIdx.x;
    const int bid = blockIdx.x;

    // ---------- data replication ----------
    {
        int idx = bid * 256 + t;                 // coarse float4 index
        if (idx < n * 16) {
            int chunk = idx & 15;
            long long cr = idx >> 4;
            float4 v = src[idx];
            float4* base = dst_data + cr * 128 + chunk; // 8 fine rows * 16 f4
#pragma unroll
            for (int j = 0; j < 8; j++) {
                base[j * 16] = v;
            }
        }
    }

    // ---------- ijk expansion ----------
    // Block covers coarse rows [bid*16, bid*16+16) -> 96 float4 of ijk output.
    if (t < 96) {
        long long q = (long long)bid * 96 + t;      // float4 index in ijk region
        if (q < (long long)n * 6) {
            long long e0 = q * 4;                   // first float element index
            float vals[4];
#pragma unroll
            for (int k = 0; k < 4; k++) {
                long long e = e0 + k;
                long long f = e / 3;                // fine voxel index
                int comp    = (int)(e - f * 3);     // 0,1,2
                long long cr = f >> 3;              // coarse row
                int sub      = (int)(f & 7);        // sub-voxel 0..7
                int c = ijk[cr * 3 + comp];
                int off = (sub >> (2 - comp)) & 1;  // meshgrid ij order
                vals[k] = (float)(2 * c + off);
            }
            dst_ijk[q] = make_float4(vals[0], vals[1], vals[2], vals[3]);
        }
    }
}

extern "C" void kernel_launch(void* const* d_in, const int* in_sizes, int n_in,
                              void* d_out, int out_size) {
    const float* coarse_data = (const float*)d_in[0];
    const int*   coarse_ijk  = (const int*)d_in[1];
    float* out = (float*)d_out;

    int n = in_sizes[0] / 64;                       // coarse voxel count
    long long data_elems = (long long)n * 8 * 64;   // fine_data float count

    float4* dst_data = (float4*)out;
    float4* dst_ijk  = (float4*)(out + data_elems);

    int blocks = (n + 15) / 16;                     // 16 coarse rows per block
    upsample_fused_kernel<<<blocks, 256>>>((const float4*)coarse_data,
                                           coarse_ijk, dst_data, dst_ijk, n);
}